// round 2
// baseline (speedup 1.0000x reference)
#include <cuda_runtime.h>
#include <cuda_bf16.h>
#include <math.h>

// Problem constants
#define NN 50000
#define EE 312500
#define DD 256
#define GN_EPS 1e-5f

// ------------------------------------------------------------------
// Device scratch (allocation-free rule: __device__ globals)
// ------------------------------------------------------------------
__device__ float g_h[NN * DD];     // GEMM output / normalized features
__device__ float g_agg[NN * DD];   // aggregation buffer / GEMM2 output
__device__ float g_stats[2 * DD];  // column sum, column sumsq
__device__ float g_AB[2 * DD];     // per-column affine: A (scale), B (shift)

// ------------------------------------------------------------------
// f32x2 packed-FMA helpers (Blackwell FFMA2 path)
// ------------------------------------------------------------------
__device__ __forceinline__ unsigned long long pack2(float x) {
    unsigned long long r;
    asm("mov.b64 %0, {%1, %1};" : "=l"(r) : "r"(__float_as_uint(x)));
    return r;
}
__device__ __forceinline__ void ffma2(unsigned long long& d,
                                      unsigned long long a,
                                      unsigned long long b) {
    asm("fma.rn.f32x2 %0, %1, %2, %0;" : "+l"(d) : "l"(a), "l"(b));
}

// ------------------------------------------------------------------
// Zero scratch + stats (+ d_out)
// ------------------------------------------------------------------
__global__ void zero_kernel(float4* __restrict__ out4) {
    const int n4 = NN * DD / 4;
    const float4 z = make_float4(0.f, 0.f, 0.f, 0.f);
    float4* agg4 = reinterpret_cast<float4*>(g_agg);
    for (int i = blockIdx.x * blockDim.x + threadIdx.x; i < n4;
         i += gridDim.x * blockDim.x) {
        agg4[i] = z;
        out4[i] = z;
    }
    int gid = blockIdx.x * blockDim.x + threadIdx.x;
    if (gid < 2 * DD / 4) reinterpret_cast<float4*>(g_stats)[gid] = z;
}

// ------------------------------------------------------------------
// GEMM: C[N,256] = A[N,256] @ W[256,256], fp32 via packed f32x2 FMA.
// 128x128 tile, BK=16, 256 threads, 8x8 per thread (as 8x4 f32x2).
// ------------------------------------------------------------------
#define BM 128
#define BN 128
#define BK 16

__global__ __launch_bounds__(256) void gemm_kernel(
    const float* __restrict__ A, const float* __restrict__ W,
    float* __restrict__ C) {
    __shared__ __align__(16) float As[BK][BM];   // stored transposed
    __shared__ __align__(16) float Bs[BK][BN];

    const int tid = threadIdx.x;
    const int tx = tid & 15;         // col group 0..15
    const int ty = tid >> 4;         // row group 0..15
    const int row0 = blockIdx.y * BM;
    const int col0 = blockIdx.x * BN;

    unsigned long long acc[8][4];
#pragma unroll
    for (int i = 0; i < 8; i++)
#pragma unroll
        for (int j = 0; j < 4; j++) acc[i][j] = 0ull;

    for (int kt = 0; kt < DD / BK; ++kt) {
        const int kb = kt * BK;
        // Load A tile: 128 rows x 16 cols = 512 float4, 2 per thread
#pragma unroll
        for (int l = 0; l < 2; l++) {
            int i = tid + l * 256;
            int r = i >> 2;       // 0..127
            int c4 = i & 3;       // 0..3
            int grow = row0 + r;
            float4 v = make_float4(0.f, 0.f, 0.f, 0.f);
            if (grow < NN)
                v = *reinterpret_cast<const float4*>(
                    A + (size_t)grow * DD + kb + c4 * 4);
            As[c4 * 4 + 0][r] = v.x;
            As[c4 * 4 + 1][r] = v.y;
            As[c4 * 4 + 2][r] = v.z;
            As[c4 * 4 + 3][r] = v.w;
        }
        // Load B tile: 16 rows x 128 cols = 512 float4, 2 per thread
#pragma unroll
        for (int l = 0; l < 2; l++) {
            int i = tid + l * 256;
            int r = i >> 5;       // 0..15
            int c4 = i & 31;      // 0..31
            float4 v = *reinterpret_cast<const float4*>(
                W + (size_t)(kb + r) * DD + col0 + c4 * 4);
            *reinterpret_cast<float4*>(&Bs[r][c4 * 4]) = v;
        }
        __syncthreads();

#pragma unroll
        for (int k = 0; k < BK; k++) {
            unsigned long long pb[4];
            const unsigned long long* bsrc =
                reinterpret_cast<const unsigned long long*>(&Bs[k][tx * 8]);
#pragma unroll
            for (int j = 0; j < 4; j++) pb[j] = bsrc[j];
#pragma unroll
            for (int i = 0; i < 8; i++) {
                unsigned long long pa = pack2(As[k][ty * 8 + i]);
#pragma unroll
                for (int j = 0; j < 4; j++) ffma2(acc[i][j], pa, pb[j]);
            }
        }
        __syncthreads();
    }

#pragma unroll
    for (int i = 0; i < 8; i++) {
        int grow = row0 + ty * 8 + i;
        if (grow < NN) {
            unsigned long long* dst = reinterpret_cast<unsigned long long*>(
                C + (size_t)grow * DD + col0 + tx * 8);
#pragma unroll
            for (int j = 0; j < 4; j++) dst[j] = acc[i][j];
        }
    }
}

// ------------------------------------------------------------------
// Edge scatter-add: agg[tgt] += feat[src], warp per edge,
// vectorized red.global.add.v4.f32 (20M vec-REDs instead of 80M scalar).
// edge_index arrives as INT32 (JAX x64 disabled downgrades int64).
// ------------------------------------------------------------------
__global__ void scatter_kernel(const float* __restrict__ feat,
                               const int* __restrict__ ei,
                               float* __restrict__ agg) {
    int e = blockIdx.x * 8 + (threadIdx.x >> 5);
    if (e >= EE) return;
    int lane = threadIdx.x & 31;
    int s = ei[e];        // source (broadcast load)
    int t = ei[EE + e];   // target
    const float4* sp =
        reinterpret_cast<const float4*>(feat + (size_t)s * DD);
    float* tp = agg + (size_t)t * DD;
#pragma unroll
    for (int i = 0; i < 2; i++) {
        int c = lane + 32 * i;              // float4 index 0..63
        float4 v = sp[c];
        asm volatile(
            "red.global.add.v4.f32 [%0], {%1, %2, %3, %4};" ::"l"(tp + c * 4),
            "f"(v.x), "f"(v.y), "f"(v.z), "f"(v.w)
            : "memory");
    }
}

// ------------------------------------------------------------------
// Column stats: sum and sumsq per feature column over all nodes.
// ------------------------------------------------------------------
#define STAT_BLOCKS 512
__global__ void colstats_kernel() {
    const int d = threadIdx.x;               // 256 threads = one column each
    const int chunk = (NN + STAT_BLOCKS - 1) / STAT_BLOCKS;
    int r0 = blockIdx.x * chunk;
    int r1 = min(NN, r0 + chunk);
    float s = 0.f, sq = 0.f;
    for (int r = r0; r < r1; ++r) {
        float v = g_agg[(size_t)r * DD + d];
        s += v;
        sq += v * v;
    }
    atomicAdd(&g_stats[d], s);
    atomicAdd(&g_stats[DD + d], sq);
}

// ------------------------------------------------------------------
// Per-column GraphNorm affine params (bias b1 folded analytically):
// out = (agg + b1 - mean*ms) * inv * w + gb  =  agg*Acol + Bcol
// ------------------------------------------------------------------
__global__ void colparams_kernel(const float* __restrict__ b1,
                                 const float* __restrict__ gw,
                                 const float* __restrict__ gb,
                                 const float* __restrict__ ms) {
    int d = threadIdx.x;
    const float invN = 1.0f / (float)NN;
    float s1 = g_stats[d];
    float s2 = g_stats[DD + d];
    float b = b1[d];
    float mr = s1 * invN;                       // raw mean of agg
    float mean = mr + b;                        // mean of (agg + b1)
    float ex2 = s2 * invN + 2.f * b * mr + b * b;  // E[(agg+b1)^2]
    float m_s = mean * ms[d];
    float var = ex2 - 2.f * m_s * mean + m_s * m_s;
    float inv = rsqrtf(var + GN_EPS);
    float Acol = gw[d] * inv;
    float Bcol = (b - m_s) * Acol + gb[d];
    g_AB[d] = Acol;
    g_AB[DD + d] = Bcol;
}

// ------------------------------------------------------------------
// Fused normalize + tanh: g_h = tanh(g_agg * A[d] + B[d])
// ------------------------------------------------------------------
__global__ void norm_tanh_kernel() {
    const int n4 = NN * DD / 4;
    const float4* in4 = reinterpret_cast<const float4*>(g_agg);
    float4* out4 = reinterpret_cast<float4*>(g_h);
    const float4* A4 = reinterpret_cast<const float4*>(g_AB);
    const float4* B4 = reinterpret_cast<const float4*>(g_AB + DD);
    for (int i = blockIdx.x * blockDim.x + threadIdx.x; i < n4;
         i += gridDim.x * blockDim.x) {
        int d4 = i & (DD / 4 - 1);
        float4 v = in4[i];
        float4 a = A4[d4];
        float4 b = B4[d4];
        float4 o;
        o.x = tanhf(fmaf(v.x, a.x, b.x));
        o.y = tanhf(fmaf(v.y, a.y, b.y));
        o.z = tanhf(fmaf(v.z, a.z, b.z));
        o.w = tanhf(fmaf(v.w, a.w, b.w));
        out4[i] = o;
    }
}

// ------------------------------------------------------------------
// Final: out = tanh(out + b2[d])   (in place on d_out)
// ------------------------------------------------------------------
__global__ void bias_tanh_kernel(float4* __restrict__ out4,
                                 const float* __restrict__ b2) {
    const int n4 = NN * DD / 4;
    const float4* B4 = reinterpret_cast<const float4*>(b2);
    for (int i = blockIdx.x * blockDim.x + threadIdx.x; i < n4;
         i += gridDim.x * blockDim.x) {
        int d4 = i & (DD / 4 - 1);
        float4 v = out4[i];
        float4 b = B4[d4];
        float4 o;
        o.x = tanhf(v.x + b.x);
        o.y = tanhf(v.y + b.y);
        o.z = tanhf(v.z + b.z);
        o.w = tanhf(v.w + b.w);
        out4[i] = o;
    }
}

// ------------------------------------------------------------------
// Launch sequence (graph-capturable: kernels only)
// ------------------------------------------------------------------
extern "C" void kernel_launch(void* const* d_in, const int* in_sizes, int n_in,
                              void* d_out, int out_size) {
    const float* x = (const float*)d_in[0];
    const int* ei = (const int*)d_in[1];
    const float* W1 = (const float*)d_in[2];
    const float* b1 = (const float*)d_in[3];
    const float* W2 = (const float*)d_in[4];
    const float* b2 = (const float*)d_in[5];
    const float* gw = (const float*)d_in[6];
    const float* gb = (const float*)d_in[7];
    const float* ms = (const float*)d_in[8];
    float* out = (float*)d_out;

    float *h, *agg;
    cudaGetSymbolAddress((void**)&h, g_h);
    cudaGetSymbolAddress((void**)&agg, g_agg);

    dim3 gemm_grid(2, (NN + BM - 1) / BM);
    int scat_blocks = (EE + 7) / 8;
    int ew_blocks = 2048;

    // 0) zero agg buffer, stats, and d_out
    zero_kernel<<<ew_blocks, 256>>>(reinterpret_cast<float4*>(out));
    // 1) h = x @ W1
    gemm_kernel<<<gemm_grid, 256>>>(x, W1, h);
    // 2) agg = scatter_add(h over edges)
    scatter_kernel<<<scat_blocks, 256>>>(h, ei, agg);
    // 3) column stats of agg
    colstats_kernel<<<STAT_BLOCKS, 256>>>();
    // 4) per-column affine params (folds b1 + GraphNorm)
    colparams_kernel<<<1, 256>>>(b1, gw, gb, ms);
    // 5) h = tanh(norm(agg))
    norm_tanh_kernel<<<ew_blocks, 256>>>();
    // 6) agg = h @ W2
    gemm_kernel<<<gemm_grid, 256>>>(h, W2, agg);
    // 7) out = scatter_add(agg over edges)   (out was zeroed in step 0)
    scatter_kernel<<<scat_blocks, 256>>>(agg, ei, out);
    // 8) out = tanh(out + b2)
    bias_tanh_kernel<<<ew_blocks, 256>>>(reinterpret_cast<float4*>(out), b2);
}

// round 4
// speedup vs baseline: 1.0186x; 1.0186x over previous
#include <cuda_runtime.h>
#include <cuda_bf16.h>
#include <math.h>

// Problem constants
#define NN 50000
#define EE 312500
#define DD 256
#define GN_EPS 1e-5f

// ------------------------------------------------------------------
// Device scratch (allocation-free rule: __device__ globals)
// ------------------------------------------------------------------
__device__ float g_h[NN * DD];      // GEMM1 out / normalized features
__device__ float g_agg[NN * DD];    // aggregation buffer / GEMM2 out
__device__ float g_stats[2 * DD];   // column sum, column sumsq
__device__ float g_AB[2 * DD];      // per-column affine: A, B
__device__ int   g_cnt[NN];         // in-degree histogram
__device__ int   g_start[NN + 1];   // CSR row starts (by target)
__device__ int   g_cursor[NN];      // fill cursors
__device__ int   g_src[EE];         // CSR payload: source node ids

// ------------------------------------------------------------------
// f32x2 packed-FMA helpers (Blackwell FFMA2 path)
// ------------------------------------------------------------------
__device__ __forceinline__ unsigned long long pack2(float x) {
    unsigned long long r;
    asm("mov.b64 %0, {%1, %1};" : "=l"(r) : "r"(__float_as_uint(x)));
    return r;
}
__device__ __forceinline__ void ffma2(unsigned long long& d,
                                      unsigned long long a,
                                      unsigned long long b) {
    asm("fma.rn.f32x2 %0, %1, %2, %0;" : "+l"(d) : "l"(a), "l"(b));
}

// ------------------------------------------------------------------
// Zero small state: g_cnt + g_stats
// ------------------------------------------------------------------
__global__ void zero_small_kernel() {
    int i = blockIdx.x * blockDim.x + threadIdx.x;
    int stride = gridDim.x * blockDim.x;
    for (int k = i; k < NN; k += stride) g_cnt[k] = 0;
    if (i < 2 * DD) g_stats[i] = 0.f;
}

// ------------------------------------------------------------------
// CSR build: histogram by target
// ------------------------------------------------------------------
__global__ void hist_kernel(const int* __restrict__ ei) {
    int e = blockIdx.x * blockDim.x + threadIdx.x;
    if (e >= EE) return;
    atomicAdd(&g_cnt[ei[EE + e]], 1);
}

// Single-block exclusive scan of g_cnt -> g_start, g_cursor
__global__ void scan_kernel() {
    __shared__ int sh[1024];
    const int t = threadIdx.x;
    const int CH = 49;                 // 1024*49 = 50176 >= NN
    int i0 = t * CH;
    int i1 = min(NN, i0 + CH);
    int s = 0;
    for (int i = i0; i < i1; ++i) s += g_cnt[i];
    sh[t] = s;
    __syncthreads();
    // inclusive Hillis-Steele scan
    for (int off = 1; off < 1024; off <<= 1) {
        int v = (t >= off) ? sh[t - off] : 0;
        __syncthreads();
        sh[t] += v;
        __syncthreads();
    }
    int run = sh[t] - s;               // exclusive prefix for this chunk
    for (int i = i0; i < i1; ++i) {
        g_start[i] = run;
        g_cursor[i] = run;
        run += g_cnt[i];
    }
    if (t == 1023) g_start[NN] = EE;
}

__global__ void fill_kernel(const int* __restrict__ ei) {
    int e = blockIdx.x * blockDim.x + threadIdx.x;
    if (e >= EE) return;
    int t = ei[EE + e];
    int pos = atomicAdd(&g_cursor[t], 1);
    g_src[pos] = ei[e];
}

// ------------------------------------------------------------------
// GEMM: C[N,256] = A[N,256] @ W[256,256] via packed f32x2 FMA.
// CTA tile 256(M) x 128(N), BK=16, 256 threads, 16x8 per thread.
// f32x2 packed along M (LDS.64 of adjacent rows = broadcast, no conflicts).
// B columns interleaved: thread tx owns cols {tx+16j} (LDS.32 banks 0..15).
// ------------------------------------------------------------------
#define BM 256
#define BN 128
#define BK 16

__global__ __launch_bounds__(256) void gemm_kernel(
    const float* __restrict__ A, const float* __restrict__ W,
    float* __restrict__ C) {
    __shared__ __align__(16) float As[BK][BM];   // transposed: As[k][m]
    __shared__ __align__(16) float Bs[BK][BN];

    const int tid = threadIdx.x;
    const int tx = tid & 15;          // n-group: cols tx + 16*j
    const int ty = tid >> 4;          // m-group: rows ty*16 .. ty*16+15
    const int row0 = blockIdx.y * BM;
    const int col0 = blockIdx.x * BN;

    unsigned long long acc[8][8];     // [m-pair][n]
#pragma unroll
    for (int i = 0; i < 8; i++)
#pragma unroll
        for (int j = 0; j < 8; j++) acc[i][j] = 0ull;

    float4 ra[4];                     // A prefetch regs (4 float4/thread)
    float4 rb[2];                     // B prefetch regs (2 float4/thread)

    // ---- global load of K-slab kt into regs ----
    auto loadG = [&](int kt) {
        const int kb = kt * BK;
#pragma unroll
        for (int l = 0; l < 4; l++) {
            int i = tid + l * 256;            // 0..1023
            int r = i >> 2;                   // 0..255
            int c4 = i & 3;                   // 0..3
            int grow = row0 + r;
            ra[l] = make_float4(0.f, 0.f, 0.f, 0.f);
            if (grow < NN)
                ra[l] = *reinterpret_cast<const float4*>(
                    A + (size_t)grow * DD + kb + c4 * 4);
        }
#pragma unroll
        for (int l = 0; l < 2; l++) {
            int i = tid + l * 256;            // 0..511
            int r = i >> 5;                   // 0..15
            int c4 = i & 31;                  // 0..31
            rb[l] = *reinterpret_cast<const float4*>(
                W + (size_t)(kb + r) * DD + col0 + c4 * 4);
        }
    };
    // ---- store regs into SMEM ----
    auto storeS = [&]() {
#pragma unroll
        for (int l = 0; l < 4; l++) {
            int i = tid + l * 256;
            int r = i >> 2;
            int c4 = i & 3;
            As[c4 * 4 + 0][r] = ra[l].x;
            As[c4 * 4 + 1][r] = ra[l].y;
            As[c4 * 4 + 2][r] = ra[l].z;
            As[c4 * 4 + 3][r] = ra[l].w;
        }
#pragma unroll
        for (int l = 0; l < 2; l++) {
            int i = tid + l * 256;
            int r = i >> 5;
            int c4 = i & 31;
            *reinterpret_cast<float4*>(&Bs[r][c4 * 4]) = rb[l];
        }
    };

    loadG(0);
    storeS();
    __syncthreads();

    for (int kt = 0; kt < DD / BK; ++kt) {
        if (kt + 1 < DD / BK) loadG(kt + 1);   // prefetch next slab

#pragma unroll
        for (int k = 0; k < BK; k++) {
            unsigned long long pa[8];
#pragma unroll
            for (int i = 0; i < 8; i++)
                pa[i] = *reinterpret_cast<const unsigned long long*>(
                    &As[k][ty * 16 + 2 * i]);
            unsigned long long pb[8];
#pragma unroll
            for (int j = 0; j < 8; j++) pb[j] = pack2(Bs[k][tx + 16 * j]);
#pragma unroll
            for (int i = 0; i < 8; i++)
#pragma unroll
                for (int j = 0; j < 8; j++) ffma2(acc[i][j], pa[i], pb[j]);
        }
        __syncthreads();
        if (kt + 1 < DD / BK) {
            storeS();
            __syncthreads();
        }
    }

    // ---- epilogue ----
#pragma unroll
    for (int i = 0; i < 8; i++) {
        float2 vals[8];
#pragma unroll
        for (int j = 0; j < 8; j++)
            vals[j] = *reinterpret_cast<float2*>(&acc[i][j]);
        int row = row0 + ty * 16 + 2 * i;
        if (row < NN) {
            float* dst = C + (size_t)row * DD + col0 + tx;
#pragma unroll
            for (int j = 0; j < 8; j++) dst[16 * j] = vals[j].x;
        }
        if (row + 1 < NN) {
            float* dst = C + (size_t)(row + 1) * DD + col0 + tx;
#pragma unroll
            for (int j = 0; j < 8; j++) dst[16 * j] = vals[j].y;
        }
    }
}

// ------------------------------------------------------------------
// CSR aggregation: out[n] = sum_{src in CSR[n]} feat[src]  (+b2, tanh)
// 64 threads per node (float4 lanes), 4 nodes per 256-thread block.
// ------------------------------------------------------------------
template <bool FINAL>
__global__ void aggregate_kernel(const float* __restrict__ feat,
                                 float* __restrict__ out,
                                 const float* __restrict__ b2) {
    int node = blockIdx.x * 4 + (threadIdx.x >> 6);
    if (node >= NN) return;
    int lane = threadIdx.x & 63;
    int d0 = lane * 4;
    int j = g_start[node];
    int j1 = g_start[node + 1];
    float4 acc = make_float4(0.f, 0.f, 0.f, 0.f);
    for (; j + 2 <= j1; j += 2) {
        int s0 = g_src[j];
        int s1 = g_src[j + 1];
        float4 v0 = *reinterpret_cast<const float4*>(
            feat + (size_t)s0 * DD + d0);
        float4 v1 = *reinterpret_cast<const float4*>(
            feat + (size_t)s1 * DD + d0);
        acc.x += v0.x + v1.x;
        acc.y += v0.y + v1.y;
        acc.z += v0.z + v1.z;
        acc.w += v0.w + v1.w;
    }
    if (j < j1) {
        int s0 = g_src[j];
        float4 v0 = *reinterpret_cast<const float4*>(
            feat + (size_t)s0 * DD + d0);
        acc.x += v0.x;
        acc.y += v0.y;
        acc.z += v0.z;
        acc.w += v0.w;
    }
    if (FINAL) {
        float4 b = *reinterpret_cast<const float4*>(b2 + d0);
        acc.x = tanhf(acc.x + b.x);
        acc.y = tanhf(acc.y + b.y);
        acc.z = tanhf(acc.z + b.z);
        acc.w = tanhf(acc.w + b.w);
    }
    *reinterpret_cast<float4*>(out + (size_t)node * DD + d0) = acc;
}

// ------------------------------------------------------------------
// Column stats (vectorized): sum / sumsq per column of g_agg.
// ------------------------------------------------------------------
#define STAT_BLOCKS 256
__global__ void colstats_kernel() {
    int q = (threadIdx.x & 63) * 4;     // column quad
    int rl = threadIdx.x >> 6;          // row lane 0..3
    float4 s = make_float4(0.f, 0.f, 0.f, 0.f);
    float4 s2 = make_float4(0.f, 0.f, 0.f, 0.f);
    for (int r = blockIdx.x * 4 + rl; r < NN; r += STAT_BLOCKS * 4) {
        float4 v = *reinterpret_cast<const float4*>(
            g_agg + (size_t)r * DD + q);
        s.x += v.x; s.y += v.y; s.z += v.z; s.w += v.w;
        s2.x += v.x * v.x; s2.y += v.y * v.y;
        s2.z += v.z * v.z; s2.w += v.w * v.w;
    }
    __shared__ float4 shs[256], shq[256];
    shs[threadIdx.x] = s;
    shq[threadIdx.x] = s2;
    __syncthreads();
    if (threadIdx.x < 128) {
        float4 a = shs[threadIdx.x + 128], b = shq[threadIdx.x + 128];
        shs[threadIdx.x].x += a.x; shs[threadIdx.x].y += a.y;
        shs[threadIdx.x].z += a.z; shs[threadIdx.x].w += a.w;
        shq[threadIdx.x].x += b.x; shq[threadIdx.x].y += b.y;
        shq[threadIdx.x].z += b.z; shq[threadIdx.x].w += b.w;
    }
    __syncthreads();
    if (threadIdx.x < 64) {
        float4 a = shs[threadIdx.x + 64], b = shq[threadIdx.x + 64];
        float4 ss = shs[threadIdx.x], qq = shq[threadIdx.x];
        ss.x += a.x; ss.y += a.y; ss.z += a.z; ss.w += a.w;
        qq.x += b.x; qq.y += b.y; qq.z += b.z; qq.w += b.w;
        int d = threadIdx.x * 4;
        atomicAdd(&g_stats[d + 0], ss.x);
        atomicAdd(&g_stats[d + 1], ss.y);
        atomicAdd(&g_stats[d + 2], ss.z);
        atomicAdd(&g_stats[d + 3], ss.w);
        atomicAdd(&g_stats[DD + d + 0], qq.x);
        atomicAdd(&g_stats[DD + d + 1], qq.y);
        atomicAdd(&g_stats[DD + d + 2], qq.z);
        atomicAdd(&g_stats[DD + d + 3], qq.w);
    }
}

// ------------------------------------------------------------------
// Per-column GraphNorm affine params (bias b1 folded analytically):
// tanh-input = agg*Acol + Bcol
// ------------------------------------------------------------------
__global__ void colparams_kernel(const float* __restrict__ b1,
                                 const float* __restrict__ gw,
                                 const float* __restrict__ gb,
                                 const float* __restrict__ ms) {
    int d = threadIdx.x;
    const float invN = 1.0f / (float)NN;
    float s1 = g_stats[d];
    float s2 = g_stats[DD + d];
    float b = b1[d];
    float mr = s1 * invN;
    float mean = mr + b;
    float ex2 = s2 * invN + 2.f * b * mr + b * b;
    float m_s = mean * ms[d];
    float var = ex2 - 2.f * m_s * mean + m_s * m_s;
    float inv = rsqrtf(var + GN_EPS);
    float Acol = gw[d] * inv;
    float Bcol = (b - m_s) * Acol + gb[d];
    g_AB[d] = Acol;
    g_AB[DD + d] = Bcol;
}

// ------------------------------------------------------------------
// Fused normalize + tanh: g_h = tanh(g_agg * A[d] + B[d])
// ------------------------------------------------------------------
__global__ void norm_tanh_kernel() {
    const int n4 = NN * DD / 4;
    const float4* in4 = reinterpret_cast<const float4*>(g_agg);
    float4* out4 = reinterpret_cast<float4*>(g_h);
    const float4* A4 = reinterpret_cast<const float4*>(g_AB);
    const float4* B4 = reinterpret_cast<const float4*>(g_AB + DD);
    for (int i = blockIdx.x * blockDim.x + threadIdx.x; i < n4;
         i += gridDim.x * blockDim.x) {
        int d4 = i & (DD / 4 - 1);
        float4 v = in4[i];
        float4 a = A4[d4];
        float4 b = B4[d4];
        float4 o;
        o.x = tanhf(fmaf(v.x, a.x, b.x));
        o.y = tanhf(fmaf(v.y, a.y, b.y));
        o.z = tanhf(fmaf(v.z, a.z, b.z));
        o.w = tanhf(fmaf(v.w, a.w, b.w));
        out4[i] = o;
    }
}

// ------------------------------------------------------------------
// Launch sequence (graph-capturable: kernels only)
// ------------------------------------------------------------------
extern "C" void kernel_launch(void* const* d_in, const int* in_sizes, int n_in,
                              void* d_out, int out_size) {
    const float* x = (const float*)d_in[0];
    const int* ei = (const int*)d_in[1];
    const float* W1 = (const float*)d_in[2];
    const float* b1 = (const float*)d_in[3];
    const float* W2 = (const float*)d_in[4];
    const float* b2 = (const float*)d_in[5];
    const float* gw = (const float*)d_in[6];
    const float* gb = (const float*)d_in[7];
    const float* ms = (const float*)d_in[8];
    float* out = (float*)d_out;

    float *h, *agg;
    cudaGetSymbolAddress((void**)&h, g_h);
    cudaGetSymbolAddress((void**)&agg, g_agg);

    const dim3 gemm_grid(DD / BN, (NN + BM - 1) / BM);  // (2, 196)
    const int eb = (EE + 255) / 256;
    const int ab = (NN + 3) / 4;

    // CSR build (edge structure, by target)
    zero_small_kernel<<<256, 256>>>();
    hist_kernel<<<eb, 256>>>(ei);
    scan_kernel<<<1, 1024>>>();
    fill_kernel<<<eb, 256>>>(ei);
    // Layer 1
    gemm_kernel<<<gemm_grid, 256>>>(x, W1, h);          // h = x @ W1
    aggregate_kernel<false><<<ab, 256>>>(h, agg, b2);   // agg = gather-sum
    colstats_kernel<<<STAT_BLOCKS, 256>>>();
    colparams_kernel<<<1, 256>>>(b1, gw, gb, ms);
    norm_tanh_kernel<<<2048, 256>>>();                  // h = tanh(norm(agg))
    // Layer 2
    gemm_kernel<<<gemm_grid, 256>>>(h, W2, agg);        // agg = h @ W2
    aggregate_kernel<true><<<ab, 256>>>(agg, out, b2);  // out = tanh(sum + b2)
}

// round 5
// speedup vs baseline: 1.3195x; 1.2954x over previous
#include <cuda_runtime.h>
#include <cuda_bf16.h>
#include <math.h>

// Problem constants
#define NN 50000
#define EE 312500
#define DD 256
#define GN_EPS 1e-5f

// ------------------------------------------------------------------
// Device scratch (allocation-free rule: __device__ globals)
// ------------------------------------------------------------------
__device__ float g_h[NN * DD];      // GEMM out (f32)
__device__ float g_agg[NN * DD];    // aggregation buffer
__device__ float g_stats[2 * DD];   // column sum, column sumsq
__device__ float g_AB[2 * DD];      // per-column affine: A, B
__device__ int   g_cnt[NN];         // in-degree histogram
__device__ int   g_start[NN + 1];   // CSR row starts (by target)
__device__ int   g_cursor[NN];      // fill cursors
__device__ int   g_src[EE];         // CSR payload: source node ids
// bf16 hi/lo split operands
__device__ __nv_bfloat16 g_xhi[NN * DD], g_xlo[NN * DD];
__device__ __nv_bfloat16 g_hhi[NN * DD], g_hlo[NN * DD];
__device__ __nv_bfloat16 g_w1h[DD * DD], g_w1l[DD * DD];  // W1^T [n][k]
__device__ __nv_bfloat16 g_w2h[DD * DD], g_w2l[DD * DD];  // W2^T [n][k]

// ------------------------------------------------------------------
// Zero small state: g_cnt + g_stats
// ------------------------------------------------------------------
__global__ void zero_small_kernel() {
    int i = blockIdx.x * blockDim.x + threadIdx.x;
    int stride = gridDim.x * blockDim.x;
    for (int k = i; k < NN; k += stride) g_cnt[k] = 0;
    if (i < 2 * DD) g_stats[i] = 0.f;
}

// ------------------------------------------------------------------
// CSR build
// ------------------------------------------------------------------
__global__ void hist_kernel(const int* __restrict__ ei) {
    int e = blockIdx.x * blockDim.x + threadIdx.x;
    if (e >= EE) return;
    atomicAdd(&g_cnt[ei[EE + e]], 1);
}

__global__ void scan_kernel() {
    __shared__ int sh[1024];
    const int t = threadIdx.x;
    const int CH = 49;                 // 1024*49 = 50176 >= NN
    int i0 = t * CH;
    int i1 = min(NN, i0 + CH);
    int s = 0;
    for (int i = i0; i < i1; ++i) s += g_cnt[i];
    sh[t] = s;
    __syncthreads();
    for (int off = 1; off < 1024; off <<= 1) {
        int v = (t >= off) ? sh[t - off] : 0;
        __syncthreads();
        sh[t] += v;
        __syncthreads();
    }
    int run = sh[t] - s;
    for (int i = i0; i < i1; ++i) {
        g_start[i] = run;
        g_cursor[i] = run;
        run += g_cnt[i];
    }
    if (t == 1023) g_start[NN] = EE;
}

__global__ void fill_kernel(const int* __restrict__ ei) {
    int e = blockIdx.x * blockDim.x + threadIdx.x;
    if (e >= EE) return;
    int t = ei[EE + e];
    int pos = atomicAdd(&g_cursor[t], 1);
    g_src[pos] = ei[e];
}

// ------------------------------------------------------------------
// hi/lo bf16 split helpers
// ------------------------------------------------------------------
__device__ __forceinline__ void split2(float a, float b,
                                       unsigned& hi, unsigned& lo) {
    __nv_bfloat16 ha = __float2bfloat16_rn(a);
    __nv_bfloat16 hb = __float2bfloat16_rn(b);
    __nv_bfloat16 la = __float2bfloat16_rn(a - __bfloat162float(ha));
    __nv_bfloat16 lb = __float2bfloat16_rn(b - __bfloat162float(hb));
    __nv_bfloat162 h2 = __nv_bfloat162(ha, hb);
    __nv_bfloat162 l2 = __nv_bfloat162(la, lb);
    hi = *reinterpret_cast<unsigned*>(&h2);
    lo = *reinterpret_cast<unsigned*>(&l2);
}

// ------------------------------------------------------------------
// Convert x -> bf16 hi/lo
// ------------------------------------------------------------------
__global__ void convert_x_kernel(const float* __restrict__ x) {
    const int n4 = NN * DD / 4;
    for (int i = blockIdx.x * blockDim.x + threadIdx.x; i < n4;
         i += gridDim.x * blockDim.x) {
        float4 v = reinterpret_cast<const float4*>(x)[i];
        unsigned h0, l0, h1, l1;
        split2(v.x, v.y, h0, l0);
        split2(v.z, v.w, h1, l1);
        reinterpret_cast<uint2*>(g_xhi)[i] = make_uint2(h0, h1);
        reinterpret_cast<uint2*>(g_xlo)[i] = make_uint2(l0, l1);
    }
}

// ------------------------------------------------------------------
// Convert W1, W2 -> transposed bf16 hi/lo: Wt[n][k] = W[k][n]
// grid 256 blocks (n), 256 threads (k)
// ------------------------------------------------------------------
__global__ void convert_w_kernel(const float* __restrict__ W1,
                                 const float* __restrict__ W2) {
    int n = blockIdx.x;
    int k = threadIdx.x;
    float w1 = W1[k * DD + n];
    float w2 = W2[k * DD + n];
    __nv_bfloat16 h1 = __float2bfloat16_rn(w1);
    __nv_bfloat16 h2 = __float2bfloat16_rn(w2);
    g_w1h[n * DD + k] = h1;
    g_w1l[n * DD + k] = __float2bfloat16_rn(w1 - __bfloat162float(h1));
    g_w2h[n * DD + k] = h2;
    g_w2l[n * DD + k] = __float2bfloat16_rn(w2 - __bfloat162float(h2));
}

// ------------------------------------------------------------------
// Tensor-core GEMM: C[N,256] = (Ahi+Alo) @ (Whi+Wlo)^T(stored [n][k])
// via mma.sync m16n8k16 bf16, 3 terms (hh, hl, lh), fp32 accum.
// CTA 128x128, 8 warps (4x2), warp tile 32x64, K-chunk 32.
// SMEM rows padded to 40 halves (80B): fragment LDS conflict-free.
// ------------------------------------------------------------------
#define GM 128
#define GN 128
#define KC 32
#define KP 40

__device__ __forceinline__ void mma_bf16(float* c, const unsigned* a,
                                         const unsigned* b) {
    asm volatile(
        "mma.sync.aligned.m16n8k16.row.col.f32.bf16.bf16.f32 "
        "{%0,%1,%2,%3}, {%4,%5,%6,%7}, {%8,%9}, {%0,%1,%2,%3};"
        : "+f"(c[0]), "+f"(c[1]), "+f"(c[2]), "+f"(c[3])
        : "r"(a[0]), "r"(a[1]), "r"(a[2]), "r"(a[3]), "r"(b[0]), "r"(b[1]));
}

__global__ __launch_bounds__(256) void gemm_mma_kernel(
    const __nv_bfloat16* __restrict__ Ah, const __nv_bfloat16* __restrict__ Al,
    const __nv_bfloat16* __restrict__ Bh, const __nv_bfloat16* __restrict__ Bl,
    float* __restrict__ C) {
    __shared__ __align__(16) __nv_bfloat16 sAh[GM * KP], sAl[GM * KP];
    __shared__ __align__(16) __nv_bfloat16 sBh[GN * KP], sBl[GN * KP];

    const int tid = threadIdx.x;
    const int warp = tid >> 5;
    const int lane = tid & 31;
    const int g = lane >> 2;        // group id 0..7
    const int tg = lane & 3;        // thread-in-group 0..3
    const int wy = warp >> 1;       // 0..3 -> m offset wy*32
    const int wx = warp & 1;        // 0..1 -> n offset wx*64
    const int row0 = blockIdx.y * GM;
    const int col0 = blockIdx.x * GN;

    float acc[2][8][4];
#pragma unroll
    for (int i = 0; i < 2; i++)
#pragma unroll
        for (int j = 0; j < 8; j++)
#pragma unroll
            for (int q = 0; q < 4; q++) acc[i][j][q] = 0.f;

    uint4 rah[2], ral[2], rbh[2], rbl[2];
    const uint4 z4 = make_uint4(0, 0, 0, 0);

    auto loadG = [&](int kc) {
#pragma unroll
        for (int l = 0; l < 2; l++) {
            int i = tid + l * 256;          // 0..511
            int r = i >> 2;                 // 0..127
            int kq = i & 3;                 // 16B quarter
            int grow = row0 + r;
            size_t aoff = (size_t)grow * DD + kc + kq * 8;
            if (grow < NN) {
                rah[l] = *reinterpret_cast<const uint4*>(Ah + aoff);
                ral[l] = *reinterpret_cast<const uint4*>(Al + aoff);
            } else {
                rah[l] = z4;
                ral[l] = z4;
            }
            size_t boff = (size_t)(col0 + r) * DD + kc + kq * 8;
            rbh[l] = *reinterpret_cast<const uint4*>(Bh + boff);
            rbl[l] = *reinterpret_cast<const uint4*>(Bl + boff);
        }
    };
    auto storeS = [&]() {
#pragma unroll
        for (int l = 0; l < 2; l++) {
            int i = tid + l * 256;
            int r = i >> 2;
            int kq = i & 3;
            int s = r * KP + kq * 8;        // 16B aligned (KP*2=80B)
            *reinterpret_cast<uint4*>(&sAh[s]) = rah[l];
            *reinterpret_cast<uint4*>(&sAl[s]) = ral[l];
            *reinterpret_cast<uint4*>(&sBh[s]) = rbh[l];
            *reinterpret_cast<uint4*>(&sBl[s]) = rbl[l];
        }
    };

    loadG(0);
    storeS();
    __syncthreads();

    for (int kc = 0; kc < DD; kc += KC) {
        if (kc + KC < DD) loadG(kc + KC);   // prefetch next chunk

#pragma unroll
        for (int ks = 0; ks < 2; ks++) {    // two k16 steps per chunk
            const int kb = ks * 16 + 2 * tg;
            unsigned ah[2][4], al[2][4];
#pragma unroll
            for (int i = 0; i < 2; i++) {
                int r = (wy * 32 + i * 16 + g) * KP + kb;
                ah[i][0] = *reinterpret_cast<const unsigned*>(&sAh[r]);
                ah[i][1] = *reinterpret_cast<const unsigned*>(&sAh[r + 8 * KP]);
                ah[i][2] = *reinterpret_cast<const unsigned*>(&sAh[r + 8]);
                ah[i][3] = *reinterpret_cast<const unsigned*>(&sAh[r + 8 * KP + 8]);
                al[i][0] = *reinterpret_cast<const unsigned*>(&sAl[r]);
                al[i][1] = *reinterpret_cast<const unsigned*>(&sAl[r + 8 * KP]);
                al[i][2] = *reinterpret_cast<const unsigned*>(&sAl[r + 8]);
                al[i][3] = *reinterpret_cast<const unsigned*>(&sAl[r + 8 * KP + 8]);
            }
            unsigned bh[8][2], bl[8][2];
#pragma unroll
            for (int j = 0; j < 8; j++) {
                int c = (wx * 64 + j * 8 + g) * KP + kb;
                bh[j][0] = *reinterpret_cast<const unsigned*>(&sBh[c]);
                bh[j][1] = *reinterpret_cast<const unsigned*>(&sBh[c + 8]);
                bl[j][0] = *reinterpret_cast<const unsigned*>(&sBl[c]);
                bl[j][1] = *reinterpret_cast<const unsigned*>(&sBl[c + 8]);
            }
            // term 1: hi*hi
#pragma unroll
            for (int i = 0; i < 2; i++)
#pragma unroll
                for (int j = 0; j < 8; j++) mma_bf16(acc[i][j], ah[i], bh[j]);
            // term 2: hi*lo
#pragma unroll
            for (int i = 0; i < 2; i++)
#pragma unroll
                for (int j = 0; j < 8; j++) mma_bf16(acc[i][j], ah[i], bl[j]);
            // term 3: lo*hi
#pragma unroll
            for (int i = 0; i < 2; i++)
#pragma unroll
                for (int j = 0; j < 8; j++) mma_bf16(acc[i][j], al[i], bh[j]);
        }
        __syncthreads();
        if (kc + KC < DD) {
            storeS();
            __syncthreads();
        }
    }

    // epilogue
#pragma unroll
    for (int i = 0; i < 2; i++) {
        int rbase = row0 + wy * 32 + i * 16 + g;
#pragma unroll
        for (int j = 0; j < 8; j++) {
            int col = col0 + wx * 64 + j * 8 + 2 * tg;
            if (rbase < NN)
                *reinterpret_cast<float2*>(C + (size_t)rbase * DD + col) =
                    make_float2(acc[i][j][0], acc[i][j][1]);
            if (rbase + 8 < NN)
                *reinterpret_cast<float2*>(C + (size_t)(rbase + 8) * DD + col) =
                    make_float2(acc[i][j][2], acc[i][j][3]);
        }
    }
}

// ------------------------------------------------------------------
// CSR aggregation: out[n] = sum_{src in CSR[n]} feat[src]  (+b2, tanh)
// ------------------------------------------------------------------
template <bool FINAL>
__global__ void aggregate_kernel(const float* __restrict__ feat,
                                 float* __restrict__ out,
                                 const float* __restrict__ b2) {
    int node = blockIdx.x * 4 + (threadIdx.x >> 6);
    if (node >= NN) return;
    int lane = threadIdx.x & 63;
    int d0 = lane * 4;
    int j = g_start[node];
    int j1 = g_start[node + 1];
    float4 acc = make_float4(0.f, 0.f, 0.f, 0.f);
    for (; j + 2 <= j1; j += 2) {
        int s0 = g_src[j];
        int s1 = g_src[j + 1];
        float4 v0 = *reinterpret_cast<const float4*>(feat + (size_t)s0 * DD + d0);
        float4 v1 = *reinterpret_cast<const float4*>(feat + (size_t)s1 * DD + d0);
        acc.x += v0.x + v1.x;
        acc.y += v0.y + v1.y;
        acc.z += v0.z + v1.z;
        acc.w += v0.w + v1.w;
    }
    if (j < j1) {
        int s0 = g_src[j];
        float4 v0 = *reinterpret_cast<const float4*>(feat + (size_t)s0 * DD + d0);
        acc.x += v0.x;
        acc.y += v0.y;
        acc.z += v0.z;
        acc.w += v0.w;
    }
    if (FINAL) {
        float4 b = *reinterpret_cast<const float4*>(b2 + d0);
        acc.x = tanhf(acc.x + b.x);
        acc.y = tanhf(acc.y + b.y);
        acc.z = tanhf(acc.z + b.z);
        acc.w = tanhf(acc.w + b.w);
    }
    *reinterpret_cast<float4*>(out + (size_t)node * DD + d0) = acc;
}

// ------------------------------------------------------------------
// Column stats (vectorized): sum / sumsq per column of g_agg.
// ------------------------------------------------------------------
#define STAT_BLOCKS 256
__global__ void colstats_kernel() {
    int q = (threadIdx.x & 63) * 4;
    int rl = threadIdx.x >> 6;
    float4 s = make_float4(0.f, 0.f, 0.f, 0.f);
    float4 s2 = make_float4(0.f, 0.f, 0.f, 0.f);
    for (int r = blockIdx.x * 4 + rl; r < NN; r += STAT_BLOCKS * 4) {
        float4 v = *reinterpret_cast<const float4*>(g_agg + (size_t)r * DD + q);
        s.x += v.x; s.y += v.y; s.z += v.z; s.w += v.w;
        s2.x += v.x * v.x; s2.y += v.y * v.y;
        s2.z += v.z * v.z; s2.w += v.w * v.w;
    }
    __shared__ float4 shs[256], shq[256];
    shs[threadIdx.x] = s;
    shq[threadIdx.x] = s2;
    __syncthreads();
    if (threadIdx.x < 128) {
        float4 a = shs[threadIdx.x + 128], b = shq[threadIdx.x + 128];
        shs[threadIdx.x].x += a.x; shs[threadIdx.x].y += a.y;
        shs[threadIdx.x].z += a.z; shs[threadIdx.x].w += a.w;
        shq[threadIdx.x].x += b.x; shq[threadIdx.x].y += b.y;
        shq[threadIdx.x].z += b.z; shq[threadIdx.x].w += b.w;
    }
    __syncthreads();
    if (threadIdx.x < 64) {
        float4 a = shs[threadIdx.x + 64], b = shq[threadIdx.x + 64];
        float4 ss = shs[threadIdx.x], qq = shq[threadIdx.x];
        ss.x += a.x; ss.y += a.y; ss.z += a.z; ss.w += a.w;
        qq.x += b.x; qq.y += b.y; qq.z += b.z; qq.w += b.w;
        int d = threadIdx.x * 4;
        atomicAdd(&g_stats[d + 0], ss.x);
        atomicAdd(&g_stats[d + 1], ss.y);
        atomicAdd(&g_stats[d + 2], ss.z);
        atomicAdd(&g_stats[d + 3], ss.w);
        atomicAdd(&g_stats[DD + d + 0], qq.x);
        atomicAdd(&g_stats[DD + d + 1], qq.y);
        atomicAdd(&g_stats[DD + d + 2], qq.z);
        atomicAdd(&g_stats[DD + d + 3], qq.w);
    }
}

// ------------------------------------------------------------------
// Per-column GraphNorm affine params (b1 folded analytically)
// ------------------------------------------------------------------
__global__ void colparams_kernel(const float* __restrict__ b1,
                                 const float* __restrict__ gw,
                                 const float* __restrict__ gb,
                                 const float* __restrict__ ms) {
    int d = threadIdx.x;
    const float invN = 1.0f / (float)NN;
    float s1 = g_stats[d];
    float s2 = g_stats[DD + d];
    float b = b1[d];
    float mr = s1 * invN;
    float mean = mr + b;
    float ex2 = s2 * invN + 2.f * b * mr + b * b;
    float m_s = mean * ms[d];
    float var = ex2 - 2.f * m_s * mean + m_s * m_s;
    float inv = rsqrtf(var + GN_EPS);
    float Acol = gw[d] * inv;
    float Bcol = (b - m_s) * Acol + gb[d];
    g_AB[d] = Acol;
    g_AB[DD + d] = Bcol;
}

// ------------------------------------------------------------------
// Fused normalize + tanh -> bf16 hi/lo (h only feeds GEMM2)
// ------------------------------------------------------------------
__global__ void norm_tanh_kernel() {
    const int n4 = NN * DD / 4;
    const float4* in4 = reinterpret_cast<const float4*>(g_agg);
    const float4* A4 = reinterpret_cast<const float4*>(g_AB);
    const float4* B4 = reinterpret_cast<const float4*>(g_AB + DD);
    for (int i = blockIdx.x * blockDim.x + threadIdx.x; i < n4;
         i += gridDim.x * blockDim.x) {
        int d4 = i & (DD / 4 - 1);
        float4 v = in4[i];
        float4 a = A4[d4];
        float4 b = B4[d4];
        float ox = tanhf(fmaf(v.x, a.x, b.x));
        float oy = tanhf(fmaf(v.y, a.y, b.y));
        float oz = tanhf(fmaf(v.z, a.z, b.z));
        float ow = tanhf(fmaf(v.w, a.w, b.w));
        unsigned h0, l0, h1, l1;
        split2(ox, oy, h0, l0);
        split2(oz, ow, h1, l1);
        reinterpret_cast<uint2*>(g_hhi)[i] = make_uint2(h0, h1);
        reinterpret_cast<uint2*>(g_hlo)[i] = make_uint2(l0, l1);
    }
}

// ------------------------------------------------------------------
// Launch sequence (graph-capturable: kernels only)
// ------------------------------------------------------------------
extern "C" void kernel_launch(void* const* d_in, const int* in_sizes, int n_in,
                              void* d_out, int out_size) {
    const float* x = (const float*)d_in[0];
    const int* ei = (const int*)d_in[1];
    const float* W1 = (const float*)d_in[2];
    const float* b1 = (const float*)d_in[3];
    const float* W2 = (const float*)d_in[4];
    const float* b2 = (const float*)d_in[5];
    const float* gw = (const float*)d_in[6];
    const float* gb = (const float*)d_in[7];
    const float* ms = (const float*)d_in[8];
    float* out = (float*)d_out;

    float *h, *agg;
    cudaGetSymbolAddress((void**)&h, g_h);
    cudaGetSymbolAddress((void**)&agg, g_agg);
    __nv_bfloat16 *xhi, *xlo, *hhi, *hlo, *w1h, *w1l, *w2h, *w2l;
    cudaGetSymbolAddress((void**)&xhi, g_xhi);
    cudaGetSymbolAddress((void**)&xlo, g_xlo);
    cudaGetSymbolAddress((void**)&hhi, g_hhi);
    cudaGetSymbolAddress((void**)&hlo, g_hlo);
    cudaGetSymbolAddress((void**)&w1h, g_w1h);
    cudaGetSymbolAddress((void**)&w1l, g_w1l);
    cudaGetSymbolAddress((void**)&w2h, g_w2h);
    cudaGetSymbolAddress((void**)&w2l, g_w2l);

    const dim3 gemm_grid(DD / GN, (NN + GM - 1) / GM);  // (2, 391)
    const int eb = (EE + 255) / 256;
    const int ab = (NN + 3) / 4;

    // CSR build + operand conversion
    zero_small_kernel<<<256, 256>>>();
    hist_kernel<<<eb, 256>>>(ei);
    convert_w_kernel<<<DD, DD>>>(W1, W2);
    convert_x_kernel<<<2048, 256>>>(x);
    scan_kernel<<<1, 1024>>>();
    fill_kernel<<<eb, 256>>>(ei);
    // Layer 1
    gemm_mma_kernel<<<gemm_grid, 256>>>(xhi, xlo, w1h, w1l, h);
    aggregate_kernel<false><<<ab, 256>>>(h, agg, b2);
    colstats_kernel<<<STAT_BLOCKS, 256>>>();
    colparams_kernel<<<1, 256>>>(b1, gw, gb, ms);
    norm_tanh_kernel<<<2048, 256>>>();                   // -> hhi/hlo
    // Layer 2
    gemm_mma_kernel<<<gemm_grid, 256>>>(hhi, hlo, w2h, w2l, h);
    aggregate_kernel<true><<<ab, 256>>>(h, out, b2);     // tanh(sum + b2)
}

// round 8
// speedup vs baseline: 1.5138x; 1.1473x over previous
#include <cuda_runtime.h>
#include <cuda_bf16.h>
#include <stdint.h>
#include <math.h>

// Problem constants
#define NN 50000
#define EE 312500
#define DD 256
#define GN_EPS 1e-5f

// ------------------------------------------------------------------
// Device scratch (allocation-free rule: __device__ globals)
// ------------------------------------------------------------------
__device__ float g_h[NN * DD];      // GEMM out (f32)
__device__ float g_agg[NN * DD];    // aggregation buffer
__device__ float g_stats[2 * DD];
__device__ float g_AB[2 * DD];
__device__ int   g_cnt[NN];
__device__ int   g_start[NN + 1];
__device__ int   g_cursor[NN];
__device__ int   g_src[EE];
// bf16 hi/lo split operands (row-major [n][k])
__device__ __nv_bfloat16 g_xhi[NN * DD], g_xlo[NN * DD];
__device__ __nv_bfloat16 g_hhi[NN * DD], g_hlo[NN * DD];
__device__ __nv_bfloat16 g_w1h[DD * DD], g_w1l[DD * DD];  // W1^T [n][k]
__device__ __nv_bfloat16 g_w2h[DD * DD], g_w2l[DD * DD];  // W2^T [n][k]

// ------------------------------------------------------------------
// Helpers
// ------------------------------------------------------------------
__device__ __forceinline__ uint32_t smem_u32(const void* p) {
    uint32_t a;
    asm("{ .reg .u64 t; cvta.to.shared.u64 t, %1; cvt.u32.u64 %0, t; }"
        : "=r"(a) : "l"(p));
    return a;
}
__device__ __forceinline__ void split2(float a, float b,
                                       unsigned& hi, unsigned& lo) {
    __nv_bfloat16 ha = __float2bfloat16_rn(a);
    __nv_bfloat16 hb = __float2bfloat16_rn(b);
    __nv_bfloat16 la = __float2bfloat16_rn(a - __bfloat162float(ha));
    __nv_bfloat16 lb = __float2bfloat16_rn(b - __bfloat162float(hb));
    __nv_bfloat162 h2 = __nv_bfloat162(ha, hb);
    __nv_bfloat162 l2 = __nv_bfloat162(la, lb);
    hi = *reinterpret_cast<unsigned*>(&h2);
    lo = *reinterpret_cast<unsigned*>(&l2);
}
__device__ __forceinline__ void ldsm_x4(uint32_t addr, unsigned* r) {
    asm volatile(
        "ldmatrix.sync.aligned.m8n8.x4.shared.b16 {%0,%1,%2,%3}, [%4];"
        : "=r"(r[0]), "=r"(r[1]), "=r"(r[2]), "=r"(r[3]) : "r"(addr));
}
__device__ __forceinline__ void mma_bf16(float* c, const unsigned* a,
                                         const unsigned* b) {
    asm volatile(
        "mma.sync.aligned.m16n8k16.row.col.f32.bf16.bf16.f32 "
        "{%0,%1,%2,%3}, {%4,%5,%6,%7}, {%8,%9}, {%0,%1,%2,%3};"
        : "+f"(c[0]), "+f"(c[1]), "+f"(c[2]), "+f"(c[3])
        : "r"(a[0]), "r"(a[1]), "r"(a[2]), "r"(a[3]), "r"(b[0]), "r"(b[1]));
}

// ------------------------------------------------------------------
// Zero small state
// ------------------------------------------------------------------
__global__ void zero_small_kernel() {
    int i = blockIdx.x * blockDim.x + threadIdx.x;
    int stride = gridDim.x * blockDim.x;
    for (int k = i; k < NN; k += stride) g_cnt[k] = 0;
    if (i < 2 * DD) g_stats[i] = 0.f;
}

// ------------------------------------------------------------------
// CSR build
// ------------------------------------------------------------------
__global__ void hist_kernel(const int* __restrict__ ei) {
    int e = blockIdx.x * blockDim.x + threadIdx.x;
    if (e >= EE) return;
    atomicAdd(&g_cnt[ei[EE + e]], 1);
}
__global__ void scan_kernel() {
    __shared__ int sh[1024];
    const int t = threadIdx.x;
    const int CH = 49;
    int i0 = t * CH, i1 = min(NN, i0 + CH);
    int s = 0;
    for (int i = i0; i < i1; ++i) s += g_cnt[i];
    sh[t] = s;
    __syncthreads();
    for (int off = 1; off < 1024; off <<= 1) {
        int v = (t >= off) ? sh[t - off] : 0;
        __syncthreads();
        sh[t] += v;
        __syncthreads();
    }
    int run = sh[t] - s;
    for (int i = i0; i < i1; ++i) {
        g_start[i] = run;
        g_cursor[i] = run;
        run += g_cnt[i];
    }
    if (t == 1023) g_start[NN] = EE;
}
__global__ void fill_kernel(const int* __restrict__ ei) {
    int e = blockIdx.x * blockDim.x + threadIdx.x;
    if (e >= EE) return;
    int t = ei[EE + e];
    int pos = atomicAdd(&g_cursor[t], 1);
    g_src[pos] = ei[e];
}

// ------------------------------------------------------------------
// Convert x -> bf16 hi/lo
// ------------------------------------------------------------------
__global__ void convert_x_kernel(const float* __restrict__ x) {
    const int n4 = NN * DD / 4;
    for (int i = blockIdx.x * blockDim.x + threadIdx.x; i < n4;
         i += gridDim.x * blockDim.x) {
        float4 v = reinterpret_cast<const float4*>(x)[i];
        unsigned h0, l0, h1, l1;
        split2(v.x, v.y, h0, l0);
        split2(v.z, v.w, h1, l1);
        reinterpret_cast<uint2*>(g_xhi)[i] = make_uint2(h0, h1);
        reinterpret_cast<uint2*>(g_xlo)[i] = make_uint2(l0, l1);
    }
}

// ------------------------------------------------------------------
// Convert W1,W2 -> transposed bf16 hi/lo: Wt[n][k] = W[k][n]
// ------------------------------------------------------------------
__global__ void convert_w_kernel(const float* __restrict__ W1,
                                 const float* __restrict__ W2) {
    int n = blockIdx.x;
    int k = threadIdx.x;
    float w1 = W1[k * DD + n];
    float w2 = W2[k * DD + n];
    __nv_bfloat16 h1 = __float2bfloat16_rn(w1);
    __nv_bfloat16 h2 = __float2bfloat16_rn(w2);
    g_w1h[n * DD + k] = h1;
    g_w1l[n * DD + k] = __float2bfloat16_rn(w1 - __bfloat162float(h1));
    g_w2h[n * DD + k] = h2;
    g_w2l[n * DD + k] = __float2bfloat16_rn(w2 - __bfloat162float(h2));
}

// ------------------------------------------------------------------
// Tensor GEMM (mma.sync + ldmatrix + cp.async double buffer)
// C[N,256] = (Ahi+Alo) @ (Whi+Wlo)^T(stored [n][k]); 3 hi/lo terms.
// CTA 128x128, 8 warps (4x2), warp tile 32x64, K-chunk 32.
// SMEM pitch KP=40 halves (80B): ldmatrix phases conflict-free.
// ------------------------------------------------------------------
#define GM 128
#define GN 128
#define KC 32
#define KP 40
#define REG_B 10240                 // bytes per array region (128*40*2)
#define SMEM_TOT (8 * REG_B)        // 2 buffers x 4 arrays = 81920

__global__ __launch_bounds__(256) void gemm_mma_kernel(
    const __nv_bfloat16* __restrict__ Ah, const __nv_bfloat16* __restrict__ Al,
    const __nv_bfloat16* __restrict__ Bh, const __nv_bfloat16* __restrict__ Bl,
    float* __restrict__ C) {
    extern __shared__ __align__(16) char smem[];
    const uint32_t sb = smem_u32(smem);
    const int tid = threadIdx.x;
    const int warp = tid >> 5, lane = tid & 31;
    const int wy = warp >> 1, wx = warp & 1;
    const int row0 = blockIdx.y * GM, col0 = blockIdx.x * GN;
    const int q = lane >> 3, r = lane & 7;

    float acc[2][8][4];
#pragma unroll
    for (int i = 0; i < 2; i++)
#pragma unroll
        for (int j = 0; j < 8; j++)
#pragma unroll
            for (int v = 0; v < 4; v++) acc[i][j][v] = 0.f;

    // ---- cp.async fill of one K-chunk into buffer b ----
    auto issue = [&](int kc, int b) {
#pragma unroll
        for (int t = 0; t < 8; t++) {
            int i = tid + t * 256;          // 0..2047
            int arr = i >> 9;               // 0:Ah 1:Al 2:Bh 3:Bl
            int rr = (i & 511) >> 2;        // row 0..127
            int kq = i & 3;                 // 16B quarter
            uint32_t dst = sb + (b * 4 + arr) * REG_B + (rr * KP + kq * 8) * 2;
            if (arr < 2) {
                int grow = row0 + rr;
                const __nv_bfloat16* g =
                    (arr == 0 ? Ah : Al) + (size_t)grow * DD + kc + kq * 8;
                int ok = (grow < NN) ? 16 : 0;   // zfill OOB rows
                asm volatile(
                    "cp.async.cg.shared.global [%0], [%1], 16, %2;" ::
                    "r"(dst), "l"(g), "r"(ok));
            } else {
                const __nv_bfloat16* g =
                    (arr == 2 ? Bh : Bl) + (size_t)(col0 + rr) * DD + kc + kq * 8;
                asm volatile(
                    "cp.async.cg.shared.global [%0], [%1], 16;" ::
                    "r"(dst), "l"(g));
            }
        }
        asm volatile("cp.async.commit_group;" ::: "memory");
    };

    issue(0, 0);
    for (int c = 0; c < DD / KC; ++c) {
        if (c < DD / KC - 1) {
            issue((c + 1) * KC, (c + 1) & 1);
            asm volatile("cp.async.wait_group 1;" ::: "memory");
        } else {
            asm volatile("cp.async.wait_group 0;" ::: "memory");
        }
        __syncthreads();

        const int b = c & 1;
        const uint32_t baseA[2] = {sb + (b * 4 + 0) * REG_B,
                                   sb + (b * 4 + 1) * REG_B};
        const uint32_t baseB[2] = {sb + (b * 4 + 2) * REG_B,
                                   sb + (b * 4 + 3) * REG_B};
#pragma unroll
        for (int ks = 0; ks < 2; ks++) {
            const int kb = ks * 16;
            unsigned af[2][2][4];      // [term][i][4]
#pragma unroll
            for (int tm = 0; tm < 2; tm++)
#pragma unroll
                for (int i = 0; i < 2; i++) {
                    int rowm = wy * 32 + i * 16 + (q & 1) * 8 + r;
                    int col = kb + (q >> 1) * 8;
                    ldsm_x4(baseA[tm] + (rowm * KP + col) * 2, af[tm][i]);
                }
            unsigned bf[2][4][4];      // [term][j2][4]
#pragma unroll
            for (int tm = 0; tm < 2; tm++)
#pragma unroll
                for (int j2 = 0; j2 < 4; j2++) {
                    int nn = wx * 64 + j2 * 16 + (q >> 1) * 8 + r;
                    int col = kb + (q & 1) * 8;
                    ldsm_x4(baseB[tm] + (nn * KP + col) * 2, bf[tm][j2]);
                }
            // hi*hi
#pragma unroll
            for (int i = 0; i < 2; i++)
#pragma unroll
                for (int j = 0; j < 8; j++)
                    mma_bf16(acc[i][j], af[0][i], &bf[0][j >> 1][(j & 1) * 2]);
            // hi*lo
#pragma unroll
            for (int i = 0; i < 2; i++)
#pragma unroll
                for (int j = 0; j < 8; j++)
                    mma_bf16(acc[i][j], af[0][i], &bf[1][j >> 1][(j & 1) * 2]);
            // lo*hi
#pragma unroll
            for (int i = 0; i < 2; i++)
#pragma unroll
                for (int j = 0; j < 8; j++)
                    mma_bf16(acc[i][j], af[1][i], &bf[0][j >> 1][(j & 1) * 2]);
        }
        __syncthreads();
    }

    // epilogue (c-frag: rows lane>>2 and +8, cols 2*(lane&3))
    const int g2 = lane >> 2, tg = lane & 3;
#pragma unroll
    for (int i = 0; i < 2; i++) {
        int rbase = row0 + wy * 32 + i * 16 + g2;
#pragma unroll
        for (int j = 0; j < 8; j++) {
            int col = col0 + wx * 64 + j * 8 + 2 * tg;
            if (rbase < NN)
                *reinterpret_cast<float2*>(C + (size_t)rbase * DD + col) =
                    make_float2(acc[i][j][0], acc[i][j][1]);
            if (rbase + 8 < NN)
                *reinterpret_cast<float2*>(C + (size_t)(rbase + 8) * DD + col) =
                    make_float2(acc[i][j][2], acc[i][j][3]);
        }
    }
}

// ------------------------------------------------------------------
// CSR aggregation: out[n] = sum_{src in CSR[n]} feat[src]  (+b2, tanh)
// ------------------------------------------------------------------
template <bool FINAL>
__global__ void aggregate_kernel(const float* __restrict__ feat,
                                 float* __restrict__ out,
                                 const float* __restrict__ b2) {
    int node = blockIdx.x * 4 + (threadIdx.x >> 6);
    if (node >= NN) return;
    int d0 = (threadIdx.x & 63) * 4;
    int j = g_start[node];
    int j1 = g_start[node + 1];
    float4 acc = make_float4(0.f, 0.f, 0.f, 0.f);
    for (; j + 2 <= j1; j += 2) {
        int s0 = g_src[j], s1 = g_src[j + 1];
        float4 v0 = *reinterpret_cast<const float4*>(feat + (size_t)s0 * DD + d0);
        float4 v1 = *reinterpret_cast<const float4*>(feat + (size_t)s1 * DD + d0);
        acc.x += v0.x + v1.x;
        acc.y += v0.y + v1.y;
        acc.z += v0.z + v1.z;
        acc.w += v0.w + v1.w;
    }
    if (j < j1) {
        float4 v0 = *reinterpret_cast<const float4*>(
            feat + (size_t)g_src[j] * DD + d0);
        acc.x += v0.x; acc.y += v0.y; acc.z += v0.z; acc.w += v0.w;
    }
    if (FINAL) {
        float4 b = *reinterpret_cast<const float4*>(b2 + d0);
        acc.x = tanhf(acc.x + b.x);
        acc.y = tanhf(acc.y + b.y);
        acc.z = tanhf(acc.z + b.z);
        acc.w = tanhf(acc.w + b.w);
    }
    *reinterpret_cast<float4*>(out + (size_t)node * DD + d0) = acc;
}

// ------------------------------------------------------------------
// Column stats
// ------------------------------------------------------------------
#define STAT_BLOCKS 256
__global__ void colstats_kernel() {
    int qd = (threadIdx.x & 63) * 4;
    int rl = threadIdx.x >> 6;
    float4 s = make_float4(0.f, 0.f, 0.f, 0.f);
    float4 s2 = make_float4(0.f, 0.f, 0.f, 0.f);
    for (int r = blockIdx.x * 4 + rl; r < NN; r += STAT_BLOCKS * 4) {
        float4 v = *reinterpret_cast<const float4*>(g_agg + (size_t)r * DD + qd);
        s.x += v.x; s.y += v.y; s.z += v.z; s.w += v.w;
        s2.x += v.x * v.x; s2.y += v.y * v.y;
        s2.z += v.z * v.z; s2.w += v.w * v.w;
    }
    __shared__ float4 shs[256], shq[256];
    shs[threadIdx.x] = s;
    shq[threadIdx.x] = s2;
    __syncthreads();
    if (threadIdx.x < 128) {
        float4 a = shs[threadIdx.x + 128], b = shq[threadIdx.x + 128];
        shs[threadIdx.x].x += a.x; shs[threadIdx.x].y += a.y;
        shs[threadIdx.x].z += a.z; shs[threadIdx.x].w += a.w;
        shq[threadIdx.x].x += b.x; shq[threadIdx.x].y += b.y;
        shq[threadIdx.x].z += b.z; shq[threadIdx.x].w += b.w;
    }
    __syncthreads();
    if (threadIdx.x < 64) {
        float4 a = shs[threadIdx.x + 64], b = shq[threadIdx.x + 64];
        float4 ss = shs[threadIdx.x], qq = shq[threadIdx.x];
        ss.x += a.x; ss.y += a.y; ss.z += a.z; ss.w += a.w;
        qq.x += b.x; qq.y += b.y; qq.z += b.z; qq.w += b.w;
        int d = threadIdx.x * 4;
        atomicAdd(&g_stats[d + 0], ss.x);
        atomicAdd(&g_stats[d + 1], ss.y);
        atomicAdd(&g_stats[d + 2], ss.z);
        atomicAdd(&g_stats[d + 3], ss.w);
        atomicAdd(&g_stats[DD + d + 0], qq.x);
        atomicAdd(&g_stats[DD + d + 1], qq.y);
        atomicAdd(&g_stats[DD + d + 2], qq.z);
        atomicAdd(&g_stats[DD + d + 3], qq.w);
    }
}

// ------------------------------------------------------------------
// Per-column GraphNorm affine params (b1 folded analytically)
// ------------------------------------------------------------------
__global__ void colparams_kernel(const float* __restrict__ b1,
                                 const float* __restrict__ gw,
                                 const float* __restrict__ gb,
                                 const float* __restrict__ ms) {
    int d = threadIdx.x;
    const float invN = 1.0f / (float)NN;
    float s1 = g_stats[d];
    float s2 = g_stats[DD + d];
    float b = b1[d];
    float mr = s1 * invN;
    float mean = mr + b;
    float ex2 = s2 * invN + 2.f * b * mr + b * b;
    float m_s = mean * ms[d];
    float var = ex2 - 2.f * m_s * mean + m_s * m_s;
    float inv = rsqrtf(var + GN_EPS);
    float Acol = gw[d] * inv;
    float Bcol = (b - m_s) * Acol + gb[d];
    g_AB[d] = Acol;
    g_AB[DD + d] = Bcol;
}

// ------------------------------------------------------------------
// Fused normalize + tanh -> bf16 hi/lo (h only feeds GEMM2)
// ------------------------------------------------------------------
__global__ void norm_tanh_kernel() {
    const int n4 = NN * DD / 4;
    const float4* in4 = reinterpret_cast<const float4*>(g_agg);
    const float4* A4 = reinterpret_cast<const float4*>(g_AB);
    const float4* B4 = reinterpret_cast<const float4*>(g_AB + DD);
    for (int i = blockIdx.x * blockDim.x + threadIdx.x; i < n4;
         i += gridDim.x * blockDim.x) {
        int d4 = i & (DD / 4 - 1);
        float4 v = in4[i];
        float4 a = A4[d4];
        float4 b = B4[d4];
        float ox = tanhf(fmaf(v.x, a.x, b.x));
        float oy = tanhf(fmaf(v.y, a.y, b.y));
        float oz = tanhf(fmaf(v.z, a.z, b.z));
        float ow = tanhf(fmaf(v.w, a.w, b.w));
        unsigned h0, l0, h1, l1;
        split2(ox, oy, h0, l0);
        split2(oz, ow, h1, l1);
        reinterpret_cast<uint2*>(g_hhi)[i] = make_uint2(h0, h1);
        reinterpret_cast<uint2*>(g_hlo)[i] = make_uint2(l0, l1);
    }
}

// ------------------------------------------------------------------
// Launch sequence (graph-capturable: kernels only)
// ------------------------------------------------------------------
extern "C" void kernel_launch(void* const* d_in, const int* in_sizes, int n_in,
                              void* d_out, int out_size) {
    const float* x = (const float*)d_in[0];
    const int* ei = (const int*)d_in[1];
    const float* W1 = (const float*)d_in[2];
    const float* b1 = (const float*)d_in[3];
    const float* W2 = (const float*)d_in[4];
    const float* b2 = (const float*)d_in[5];
    const float* gw = (const float*)d_in[6];
    const float* gb = (const float*)d_in[7];
    const float* ms = (const float*)d_in[8];
    float* out = (float*)d_out;

    float *h, *agg;
    cudaGetSymbolAddress((void**)&h, g_h);
    cudaGetSymbolAddress((void**)&agg, g_agg);
    __nv_bfloat16 *xhi, *xlo, *hhi, *hlo, *w1h, *w1l, *w2h, *w2l;
    cudaGetSymbolAddress((void**)&xhi, g_xhi);
    cudaGetSymbolAddress((void**)&xlo, g_xlo);
    cudaGetSymbolAddress((void**)&hhi, g_hhi);
    cudaGetSymbolAddress((void**)&hlo, g_hlo);
    cudaGetSymbolAddress((void**)&w1h, g_w1h);
    cudaGetSymbolAddress((void**)&w1l, g_w1l);
    cudaGetSymbolAddress((void**)&w2h, g_w2h);
    cudaGetSymbolAddress((void**)&w2l, g_w2l);

    cudaFuncSetAttribute(gemm_mma_kernel,
                         cudaFuncAttributeMaxDynamicSharedMemorySize,
                         SMEM_TOT);

    const dim3 gemm_grid(DD / GN, (NN + GM - 1) / GM);  // (2, 391)
    const int eb = (EE + 255) / 256;
    const int ab = (NN + 3) / 4;

    // CSR build + operand conversion
    zero_small_kernel<<<256, 256>>>();
    hist_kernel<<<eb, 256>>>(ei);
    convert_w_kernel<<<DD, DD>>>(W1, W2);
    convert_x_kernel<<<2048, 256>>>(x);
    scan_kernel<<<1, 1024>>>();
    fill_kernel<<<eb, 256>>>(ei);
    // Layer 1
    gemm_mma_kernel<<<gemm_grid, 256, SMEM_TOT>>>(xhi, xlo, w1h, w1l, h);
    aggregate_kernel<false><<<ab, 256>>>(h, agg, b2);
    colstats_kernel<<<STAT_BLOCKS, 256>>>();
    colparams_kernel<<<1, 256>>>(b1, gw, gb, ms);
    norm_tanh_kernel<<<2048, 256>>>();                   // -> hhi/hlo
    // Layer 2
    gemm_mma_kernel<<<gemm_grid, 256, SMEM_TOT>>>(hhi, hlo, w2h, w2l, h);
    aggregate_kernel<true><<<ab, 256>>>(h, out, b2);
}